// round 3
// baseline (speedup 1.0000x reference)
#include <cuda_runtime.h>
#include <cuda_bf16.h>

// Problem shape (fixed): B=4, S=2048 -> N=8192 rows, D=4096, O=4096, k=1024.
#define N_MAX 8192
#define O_MAX 4096
#define CAP   32          // max boundary candidates per row (avg ~1.3)
#define BAND_EPS 1e-4f    // >> fp32 gemm error bound (~2e-5 max)

// Scratch (device globals are the sanctioned alternative to cudaMalloc):
__device__ float         g_router[(size_t)N_MAX * O_MAX];
__device__ unsigned char g_mask  [(size_t)N_MAX * O_MAX];
__device__ int           g_cand  [(size_t)N_MAX * CAP];
__device__ double        g_exact [(size_t)N_MAX * CAP];
__device__ int           g_need  [N_MAX];
__device__ int           g_ccnt  [N_MAX];

// ---------------------------------------------------------------------------
// fp32 SGEMM:  C[n,o] = dot(A[n,:], W[o,:]) + bias[o]
// mode 0: C = acc + bias          (router pass)
// mode 1: C = (acc + bias) * mask (orig pass)
// ---------------------------------------------------------------------------
#define BM 128
#define BN 128
#define BK 8
#define TM 8
#define TN 8

__global__ __launch_bounds__(256)
void gemm_nt_kernel(const float* __restrict__ A,
                    const float* __restrict__ W,
                    const float* __restrict__ bias,
                    float* __restrict__ C,
                    const unsigned char* __restrict__ mask,
                    int N, int O, int D, int mode)
{
    __shared__ float As[BK][BM];
    __shared__ float Bs[BK][BN];

    const int bm = blockIdx.y * BM;
    const int bn = blockIdx.x * BN;
    const int tid = threadIdx.x;
    const int tx = tid & 15;
    const int ty = tid >> 4;

    const int loadRow = tid >> 1;
    const int loadCol = (tid & 1) * 4;

    const bool aRowOk = (bm + loadRow) < N;
    const bool wRowOk = (bn + loadRow) < O;
    const float* Aptr = A + (size_t)(bm + loadRow) * D + loadCol;
    const float* Wptr = W + (size_t)(bn + loadRow) * D + loadCol;

    float acc[TM][TN];
#pragma unroll
    for (int i = 0; i < TM; i++)
#pragma unroll
        for (int j = 0; j < TN; j++) acc[i][j] = 0.0f;

    for (int k0 = 0; k0 < D; k0 += BK) {
        float4 av = aRowOk ? *(const float4*)(Aptr + k0) : make_float4(0.f, 0.f, 0.f, 0.f);
        float4 wv = wRowOk ? *(const float4*)(Wptr + k0) : make_float4(0.f, 0.f, 0.f, 0.f);
        As[loadCol + 0][loadRow] = av.x;
        As[loadCol + 1][loadRow] = av.y;
        As[loadCol + 2][loadRow] = av.z;
        As[loadCol + 3][loadRow] = av.w;
        Bs[loadCol + 0][loadRow] = wv.x;
        Bs[loadCol + 1][loadRow] = wv.y;
        Bs[loadCol + 2][loadRow] = wv.z;
        Bs[loadCol + 3][loadRow] = wv.w;
        __syncthreads();

#pragma unroll
        for (int kk = 0; kk < BK; kk++) {
            float a[TM], b[TN];
            float4 a0 = *(const float4*)&As[kk][ty * TM];
            float4 a1 = *(const float4*)&As[kk][ty * TM + 4];
            a[0] = a0.x; a[1] = a0.y; a[2] = a0.z; a[3] = a0.w;
            a[4] = a1.x; a[5] = a1.y; a[6] = a1.z; a[7] = a1.w;
            float4 b0 = *(const float4*)&Bs[kk][tx * TN];
            float4 b1 = *(const float4*)&Bs[kk][tx * TN + 4];
            b[0] = b0.x; b[1] = b0.y; b[2] = b0.z; b[3] = b0.w;
            b[4] = b1.x; b[5] = b1.y; b[6] = b1.z; b[7] = b1.w;
#pragma unroll
            for (int i = 0; i < TM; i++)
#pragma unroll
                for (int j = 0; j < TN; j++)
                    acc[i][j] = fmaf(a[i], b[j], acc[i][j]);
        }
        __syncthreads();
    }

#pragma unroll
    for (int i = 0; i < TM; i++) {
        const int row = bm + ty * TM + i;
        if (row >= N) continue;
#pragma unroll
        for (int j = 0; j < TN; j++) {
            const int col = bn + tx * TN + j;
            if (col >= O) continue;
            float v = acc[i][j] + bias[col];
            const size_t idx = (size_t)row * O + col;
            if (mode == 0) C[idx] = v;
            else           C[idx] = mask[idx] ? v : 0.0f;
        }
    }
}

// ---------------------------------------------------------------------------
// Per-row top-k selection with boundary-band candidate extraction.
// Radix-selects the exact fp32 k-th value T, writes definite in/out mask,
// and records elements within +-BAND_EPS of T for exact fp64 re-ranking.
// ---------------------------------------------------------------------------
#define TPK_THREADS 256

__device__ __forceinline__ unsigned int f2key(float f) {
    unsigned int b = __float_as_uint(f);
    return (b & 0x80000000u) ? ~b : (b | 0x80000000u);
}
__device__ __forceinline__ float key2f(unsigned int u) {
    unsigned int b = (u & 0x80000000u) ? (u ^ 0x80000000u) : ~u;
    return __uint_as_float(b);
}

__global__ __launch_bounds__(TPK_THREADS)
void topk_select_kernel(const float* __restrict__ R,
                        unsigned char* __restrict__ mask,
                        int O, int k)
{
    __shared__ float s[O_MAX];
    __shared__ unsigned int hist[256];
    __shared__ unsigned int s_prefix, s_prefMask, s_rem;
    __shared__ int s_G, s_C, s_fallback;

    const int row = blockIdx.x;
    const float* r = R + (size_t)row * O;
    unsigned char* mrow = mask + (size_t)row * O;

    for (int i = threadIdx.x; i < O; i += TPK_THREADS) s[i] = r[i];
    if (threadIdx.x == 0) {
        s_prefix = 0u; s_prefMask = 0u; s_rem = (unsigned int)k;
        s_G = 0; s_C = 0; s_fallback = 0;
    }
    __syncthreads();

    // 4-pass radix select (MSB->LSB) for the exact fp32 k-th largest value.
    for (int pass = 0; pass < 4; pass++) {
        const int shift = 24 - 8 * pass;
        hist[threadIdx.x] = 0u;
        __syncthreads();
        const unsigned int pm = s_prefMask;
        const unsigned int pv = s_prefix;
        for (int i = threadIdx.x; i < O; i += TPK_THREADS) {
            unsigned int u = f2key(s[i]);
            if ((u & pm) == pv)
                atomicAdd(&hist[(u >> shift) & 0xFFu], 1u);
        }
        __syncthreads();
        if (threadIdx.x == 0) {
            unsigned int cum = 0;
            int b = 255;
            for (; b >= 0; b--) {
                unsigned int c = hist[b];
                if (cum + c >= s_rem) { s_rem -= cum; break; }
                cum += c;
            }
            if (b < 0) b = 0;
            s_prefix |= ((unsigned int)b) << shift;
            s_prefMask |= 0xFFu << shift;
        }
        __syncthreads();
    }

    const unsigned int kT = s_prefix;
    const float T = key2f(kT);
    const float hi = T + BAND_EPS;
    const float lo = T - BAND_EPS;

    // Band classification: definite-in / candidate / definite-out.
    for (int i = threadIdx.x; i < O; i += TPK_THREADS) {
        float v = s[i];
        if (v > hi) {
            mrow[i] = 1;
            atomicAdd(&s_G, 1);
        } else {
            mrow[i] = 0;
            if (v >= lo) {
                int p = atomicAdd(&s_C, 1);
                if (p < CAP) g_cand[(size_t)row * CAP + p] = i;
            }
        }
    }
    __syncthreads();

    if (threadIdx.x == 0) {
        if (s_C <= CAP) {
            g_ccnt[row] = s_C;
            int need = k - s_G;
            if (need < 0) need = 0;
            if (need > s_C) need = s_C;
            g_need[row] = need;
        } else {
            s_fallback = 1;          // pathological tie explosion: fp32 rule
            g_ccnt[row] = 0;
            g_need[row] = 0;
        }
    }
    __syncthreads();

    if (s_fallback) {
        for (int i = threadIdx.x; i < O; i += TPK_THREADS)
            mrow[i] = (f2key(s[i]) > kT) ? 1 : 0;
        __syncthreads();
        if (threadIdx.x == 0) {
            int q = (int)s_rem;
            for (int i = 0; i < O && q > 0; i++)
                if (f2key(s[i]) == kT) { mrow[i] = 1; q--; }
        }
    }
}

// ---------------------------------------------------------------------------
// Exact fp64 router score for each boundary candidate.
// grid = (CAP, N); inactive blocks exit immediately.
// ---------------------------------------------------------------------------
__global__ __launch_bounds__(256)
void exact_score_kernel(const float* __restrict__ x,
                        const float* __restrict__ W,
                        const float* __restrict__ bias,
                        int D, int O)
{
    const int row = blockIdx.y;
    const int slot = blockIdx.x;
    if (slot >= g_ccnt[row]) return;
    const int col = g_cand[(size_t)row * CAP + slot];

    const float* xr = x + (size_t)row * D;
    const float* wr = W + (size_t)col * D;

    double acc = 0.0;
    for (int i = threadIdx.x; i < D; i += 256)
        acc += (double)xr[i] * (double)wr[i];

    __shared__ double red[256];
    red[threadIdx.x] = acc;
    __syncthreads();
    for (int off = 128; off > 0; off >>= 1) {
        if (threadIdx.x < off) red[threadIdx.x] += red[threadIdx.x + off];
        __syncthreads();
    }
    if (threadIdx.x == 0)
        g_exact[(size_t)row * CAP + slot] = red[0] + (double)bias[col];
}

// ---------------------------------------------------------------------------
// Finalize: rank candidates by exact score (desc, index asc on ties) and
// set mask for the top 'need' of them.
// ---------------------------------------------------------------------------
__global__ void finalize_kernel(unsigned char* __restrict__ mask, int O)
{
    const int row = blockIdx.x;
    if (threadIdx.x != 0) return;
    int C = g_ccnt[row];
    int need = g_need[row];
    if (C <= 0 || need <= 0) return;
    if (C > CAP) C = CAP;
    if (need > C) need = C;

    double sc[CAP];
    int    id[CAP];
    for (int j = 0; j < C; j++) {
        sc[j] = g_exact[(size_t)row * CAP + j];
        id[j] = g_cand [(size_t)row * CAP + j];
    }
    // insertion sort: score desc, index asc for equal scores
    for (int a = 1; a < C; a++) {
        double v = sc[a]; int vi = id[a];
        int b = a - 1;
        while (b >= 0 && (sc[b] < v || (sc[b] == v && id[b] > vi))) {
            sc[b + 1] = sc[b]; id[b + 1] = id[b]; b--;
        }
        sc[b + 1] = v; id[b + 1] = vi;
    }
    unsigned char* mrow = mask + (size_t)row * O;
    for (int j = 0; j < need; j++) mrow[id[j]] = 1;
}

// ---------------------------------------------------------------------------
// kernel_launch
// ---------------------------------------------------------------------------
extern "C" void kernel_launch(void* const* d_in, const int* in_sizes, int n_in,
                              void* d_out, int out_size)
{
    const float* x  = (const float*)d_in[0];
    const float* Wr = (const float*)d_in[1];
    const float* br = (const float*)d_in[2];
    const float* Wo = (const float*)d_in[3];
    const float* bo = (const float*)d_in[4];
    float* out = (float*)d_out;

    const int O = in_sizes[2];
    const int D = in_sizes[1] / O;
    const int N = in_sizes[0] / D;
    int k = (int)(((long long)O * 25LL) / 100LL);
    if (k < 1) k = 1;

    float* R = nullptr;
    unsigned char* M = nullptr;
    cudaGetSymbolAddress((void**)&R, g_router);
    cudaGetSymbolAddress((void**)&M, g_mask);

    dim3 block(256);
    dim3 grid((O + BN - 1) / BN, (N + BM - 1) / BM);

    // 1) Router scores (fp32)
    gemm_nt_kernel<<<grid, block>>>(x, Wr, br, R, nullptr, N, O, D, 0);

    // 2) Top-k: radix select + boundary band
    topk_select_kernel<<<N, TPK_THREADS>>>(R, M, O, k);

    // 3) Exact fp64 re-rank of boundary candidates
    {
        dim3 eg(CAP, N);
        exact_score_kernel<<<eg, 256>>>(x, Wr, br, D, O);
        finalize_kernel<<<N, 32>>>(M, O);
    }

    // 4) Original projection, masked
    gemm_nt_kernel<<<grid, block>>>(x, Wo, bo, out, M, N, O, D, 1);
}